// round 15
// baseline (speedup 1.0000x reference)
#include <cuda_runtime.h>
#include <cuda_bf16.h>
#include <math.h>
#include <stdint.h>

#define BB 4
#define SS 1024
#define DD 1024
#define D3 3072
#define DFF 4096
#define NH 16
#define DH 64
#define NL 16

__device__ float g_h[(size_t)BB * SS * DD];
__device__ float g_qkv[(size_t)BB * SS * D3];
__device__ float g_ctx[(size_t)BB * SS * DD];
__device__ float g_tmp[(size_t)BB * SS * DD];
__device__ float g_mlp[(size_t)BB * SS * DFF];

// =================== bf16 hi/lo split helpers =============================
__device__ __forceinline__ void cvt_hilo4(float4 v, uint32_t& h01, uint32_t& h23,
                                          uint32_t& l01, uint32_t& l23) {
    __nv_bfloat16 hx = __float2bfloat16(v.x);
    __nv_bfloat16 hy = __float2bfloat16(v.y);
    __nv_bfloat16 hz = __float2bfloat16(v.z);
    __nv_bfloat16 hw = __float2bfloat16(v.w);
    __nv_bfloat16 lx = __float2bfloat16(v.x - __bfloat162float(hx));
    __nv_bfloat16 ly = __float2bfloat16(v.y - __bfloat162float(hy));
    __nv_bfloat16 lz = __float2bfloat16(v.z - __bfloat162float(hz));
    __nv_bfloat16 lw = __float2bfloat16(v.w - __bfloat162float(hw));
    h01 = ((uint32_t)__bfloat16_as_ushort(hy) << 16) | __bfloat16_as_ushort(hx);
    h23 = ((uint32_t)__bfloat16_as_ushort(hw) << 16) | __bfloat16_as_ushort(hz);
    l01 = ((uint32_t)__bfloat16_as_ushort(ly) << 16) | __bfloat16_as_ushort(lx);
    l23 = ((uint32_t)__bfloat16_as_ushort(lw) << 16) | __bfloat16_as_ushort(lz);
}

__device__ __forceinline__ uint32_t packpair(float x, float y, uint32_t& lo) {
    __nv_bfloat16 hx = __float2bfloat16(x);
    __nv_bfloat16 hy = __float2bfloat16(y);
    __nv_bfloat16 lx = __float2bfloat16(x - __bfloat162float(hx));
    __nv_bfloat16 ly = __float2bfloat16(y - __bfloat162float(hy));
    lo = ((uint32_t)__bfloat16_as_ushort(ly) << 16) | __bfloat16_as_ushort(lx);
    return ((uint32_t)__bfloat16_as_ushort(hy) << 16) | __bfloat16_as_ushort(hx);
}

__device__ __forceinline__ void mma16816(float* c, const uint32_t* a, const uint32_t* b) {
    asm volatile(
        "mma.sync.aligned.m16n8k16.row.col.f32.bf16.bf16.f32 "
        "{%0,%1,%2,%3},{%4,%5,%6,%7},{%8,%9},{%0,%1,%2,%3};"
        : "+f"(c[0]), "+f"(c[1]), "+f"(c[2]), "+f"(c[3])
        : "r"(a[0]), "r"(a[1]), "r"(a[2]), "r"(a[3]), "r"(b[0]), "r"(b[1]));
}

// ============== tensor-core GEMM: C = A[M,K] @ W[N,K]^T + bias =============
// bf16 hi/lo 3-MMA. Tile 128x64, 128 threads (4 warps, warp 32x64),
// K chunk 32, double-buffered -> 2 CTAs/SM (cross-CTA bubble hiding).
// Buffer (RP=80 pitch): Ah@0 (10240) | Al@10240 | Bh@20480 (5120) | Bl@25600
// -> TG_BUF = 30720 B, two buffers = 61440 B.
#define TG_BUF  30720
#define TG_SMEM (2 * TG_BUF)
#define RP      80   // row pitch in bytes - conflict-free fragment loads

template <int EPI>
__global__ __launch_bounds__(128, 2) void tgemm(
    const float* __restrict__ A, int lda,
    const float* __restrict__ W, int ldw,
    const float* __restrict__ bias,
    const float* __restrict__ R, int ldr,
    float* __restrict__ C, int ldc,
    int K)
{
    extern __shared__ __align__(16) char smem[];
    const int tid = threadIdx.x;
    const int lane = tid & 31;
    const int wid = tid >> 5;           // 0..3 -> m offset wid*32
    const int row0 = blockIdx.y * 128;
    const int col0 = blockIdx.x * 64;

    // staging: A one full row per thread (32 f/chunk); B 2 threads/row
    const float* Ag = A + (size_t)(row0 + tid) * lda;
    const int srowB = tid >> 1;
    const int kbB = (tid & 1) * 16;
    const float* Wg = W + (size_t)(col0 + srowB) * ldw + kbB;

    float4 Areg[8], Breg[4];
    const int nc = K >> 5;

#pragma unroll
    for (int i = 0; i < 8; i++) Areg[i] = *(const float4*)(Ag + i * 4);
#pragma unroll
    for (int i = 0; i < 4; i++) Breg[i] = *(const float4*)(Wg + i * 4);
    {
        char* bb = smem;
        const uint32_t oa = (uint32_t)tid * RP;
#pragma unroll
        for (int i = 0; i < 8; i++) {
            uint32_t h01, h23, l01, l23;
            cvt_hilo4(Areg[i], h01, h23, l01, l23);
            *(uint32_t*)(bb + oa + i * 8) = h01;
            *(uint32_t*)(bb + oa + i * 8 + 4) = h23;
            *(uint32_t*)(bb + 10240 + oa + i * 8) = l01;
            *(uint32_t*)(bb + 10240 + oa + i * 8 + 4) = l23;
        }
        const uint32_t ob = (uint32_t)srowB * RP + (uint32_t)kbB * 2;
#pragma unroll
        for (int i = 0; i < 4; i++) {
            uint32_t h01, h23, l01, l23;
            cvt_hilo4(Breg[i], h01, h23, l01, l23);
            *(uint32_t*)(bb + 20480 + ob + i * 8) = h01;
            *(uint32_t*)(bb + 20480 + ob + i * 8 + 4) = h23;
            *(uint32_t*)(bb + 25600 + ob + i * 8) = l01;
            *(uint32_t*)(bb + 25600 + ob + i * 8 + 4) = l23;
        }
    }
    __syncthreads();

    float acc[2][8][4];
#pragma unroll
    for (int mi = 0; mi < 2; mi++)
#pragma unroll
        for (int ni = 0; ni < 8; ni++)
#pragma unroll
            for (int j = 0; j < 4; j++) acc[mi][ni][j] = 0.f;

    const int r = lane >> 2;
    const int q = lane & 3;

    for (int c = 0; c < nc; c++) {
        if (c + 1 < nc) {
            const int k0 = (c + 1) << 5;
#pragma unroll
            for (int i = 0; i < 8; i++) Areg[i] = *(const float4*)(Ag + k0 + i * 4);
#pragma unroll
            for (int i = 0; i < 4; i++) Breg[i] = *(const float4*)(Wg + k0 + i * 4);
        }

        const char* bb = smem + (c & 1) * TG_BUF;
#pragma unroll
        for (int ks = 0; ks < 32; ks += 16) {
            uint32_t aH[2][4], aL[2][4];
#pragma unroll
            for (int mi = 0; mi < 2; mi++) {
                const uint32_t row = (uint32_t)(wid * 32 + mi * 16 + r);
                const uint32_t o = row * RP + (uint32_t)(ks + 2 * q) * 2;
                aH[mi][0] = *(const uint32_t*)(bb + o);
                aH[mi][1] = *(const uint32_t*)(bb + o + 8 * RP);
                aH[mi][2] = *(const uint32_t*)(bb + o + 16);
                aH[mi][3] = *(const uint32_t*)(bb + o + 8 * RP + 16);
                aL[mi][0] = *(const uint32_t*)(bb + 10240 + o);
                aL[mi][1] = *(const uint32_t*)(bb + 10240 + o + 8 * RP);
                aL[mi][2] = *(const uint32_t*)(bb + 10240 + o + 16);
                aL[mi][3] = *(const uint32_t*)(bb + 10240 + o + 8 * RP + 16);
            }
            uint32_t bH[8][2], bL[8][2];
#pragma unroll
            for (int ni = 0; ni < 8; ni++) {
                const uint32_t n = (uint32_t)(ni * 8 + r);
                const uint32_t o = n * RP + (uint32_t)(ks + 2 * q) * 2;
                bH[ni][0] = *(const uint32_t*)(bb + 20480 + o);
                bH[ni][1] = *(const uint32_t*)(bb + 20480 + o + 16);
                bL[ni][0] = *(const uint32_t*)(bb + 25600 + o);
                bL[ni][1] = *(const uint32_t*)(bb + 25600 + o + 16);
            }
#pragma unroll
            for (int mi = 0; mi < 2; mi++)
#pragma unroll
                for (int ni = 0; ni < 8; ni++) {
                    mma16816(acc[mi][ni], aH[mi], bH[ni]);
                    mma16816(acc[mi][ni], aH[mi], bL[ni]);
                    mma16816(acc[mi][ni], aL[mi], bH[ni]);
                }
        }

        if (c + 1 < nc) {
            char* wb = smem + ((c + 1) & 1) * TG_BUF;
            const uint32_t oa = (uint32_t)tid * RP;
#pragma unroll
            for (int i = 0; i < 8; i++) {
                uint32_t h01, h23, l01, l23;
                cvt_hilo4(Areg[i], h01, h23, l01, l23);
                *(uint32_t*)(wb + oa + i * 8) = h01;
                *(uint32_t*)(wb + oa + i * 8 + 4) = h23;
                *(uint32_t*)(wb + 10240 + oa + i * 8) = l01;
                *(uint32_t*)(wb + 10240 + oa + i * 8 + 4) = l23;
            }
            const uint32_t ob = (uint32_t)srowB * RP + (uint32_t)kbB * 2;
#pragma unroll
            for (int i = 0; i < 4; i++) {
                uint32_t h01, h23, l01, l23;
                cvt_hilo4(Breg[i], h01, h23, l01, l23);
                *(uint32_t*)(wb + 20480 + ob + i * 8) = h01;
                *(uint32_t*)(wb + 20480 + ob + i * 8 + 4) = h23;
                *(uint32_t*)(wb + 25600 + ob + i * 8) = l01;
                *(uint32_t*)(wb + 25600 + ob + i * 8 + 4) = l23;
            }
            __syncthreads();
        }
    }

#pragma unroll
    for (int mi = 0; mi < 2; mi++) {
        const int rbase = row0 + wid * 32 + mi * 16 + r;
#pragma unroll
        for (int ni = 0; ni < 8; ni++) {
            const int col = col0 + ni * 8 + 2 * q;
            float2 bv = *(const float2*)(bias + col);
            float o0 = acc[mi][ni][0] + bv.x;
            float o1 = acc[mi][ni][1] + bv.y;
            float o2 = acc[mi][ni][2] + bv.x;
            float o3 = acc[mi][ni][3] + bv.y;
            if (EPI == 1) {
                o0 = fmaxf(o0, 0.f); o1 = fmaxf(o1, 0.f);
                o2 = fmaxf(o2, 0.f); o3 = fmaxf(o3, 0.f);
            }
            if (EPI == 2) {
                float2 r0 = *(const float2*)(R + (size_t)rbase * ldr + col);
                float2 r1 = *(const float2*)(R + (size_t)(rbase + 8) * ldr + col);
                o0 += r0.x; o1 += r0.y; o2 += r1.x; o3 += r1.y;
            }
            *(float2*)(C + (size_t)rbase * ldc + col) = make_float2(o0, o1);
            *(float2*)(C + (size_t)(rbase + 8) * ldc + col) = make_float2(o2, o3);
        }
    }
}

// ====================== fused flash attention (round-5 exact) =============
// Block: 256 threads (8 warps), q-tile 128 rows. Warp w owns rows w*16..+16.
// QH 0 / QL 20480 / KH 40960 / KL 61440 / VH 81920 / VL 102400 -> 122880 B.
#define FA_SMEM 122880

__global__ __launch_bounds__(256, 1) void flash_attn(
    const float* __restrict__ qkv, float* __restrict__ ctx)
{
    extern __shared__ __align__(16) char smem[];
    const int tid = threadIdx.x;
    const int lane = tid & 31;
    const int w = tid >> 5;
    const int r = lane >> 2;
    const int q = lane & 3;
    const int bh = blockIdx.y;
    const int b = bh >> 4;
    const int h = bh & 15;
    const int qt = gridDim.x - 1 - blockIdx.x;  // long blocks first

    const float* Qg = qkv + (size_t)b * SS * D3 + h * DH;
    const float* Kg = Qg + DD;
    const float* Vg = Qg + 2 * DD;

    // ---- load Q tile once (scaled by 1/8), hi/lo split ----
    {
        const int srow = tid >> 1;
        const int c = tid & 1;
        const float* src = Qg + (size_t)(qt * 128 + srow) * D3 + c * 32;
        char* dh = smem + c * 10240 + srow * RP;
        char* dl = smem + 20480 + c * 10240 + srow * RP;
#pragma unroll
        for (int i = 0; i < 8; i++) {
            float4 v = *(const float4*)(src + i * 4);
            v.x *= 0.125f; v.y *= 0.125f; v.z *= 0.125f; v.w *= 0.125f;
            uint32_t h01, h23, l01, l23;
            cvt_hilo4(v, h01, h23, l01, l23);
            *(uint32_t*)(dh + i * 8) = h01;
            *(uint32_t*)(dh + i * 8 + 4) = h23;
            *(uint32_t*)(dl + i * 8) = l01;
            *(uint32_t*)(dl + i * 8 + 4) = l23;
        }
    }

    float Oacc[8][4];
#pragma unroll
    for (int ni = 0; ni < 8; ni++)
#pragma unroll
        for (int j = 0; j < 4; j++) Oacc[ni][j] = 0.f;
    float m0 = -1e30f, m1 = -1e30f, l0 = 0.f, l1 = 0.f;

    for (int kt = 0; kt <= qt; kt++) {
        __syncthreads();
        // ---- K tile (hi/lo) ----
        {
            const int srow = tid >> 1;
            const int c = tid & 1;
            const float* src = Kg + (size_t)(kt * 128 + srow) * D3 + c * 32;
            char* dh = smem + 40960 + c * 10240 + srow * RP;
            char* dl = smem + 61440 + c * 10240 + srow * RP;
#pragma unroll
            for (int i = 0; i < 8; i++) {
                float4 v = *(const float4*)(src + i * 4);
                uint32_t h01, h23, l01, l23;
                cvt_hilo4(v, h01, h23, l01, l23);
                *(uint32_t*)(dh + i * 8) = h01;
                *(uint32_t*)(dh + i * 8 + 4) = h23;
                *(uint32_t*)(dl + i * 8) = l01;
                *(uint32_t*)(dl + i * 8 + 4) = l23;
            }
        }
        // ---- V tile transposed: Vs[d][s] (hi/lo), lane-consecutive d ----
        {
            const int d = tid & 63;
            const int sb = tid >> 6;
            const float* src = Vg + (size_t)(kt * 128 + sb * 32) * D3 + d;
            char* dh = smem + 81920 + sb * 5120 + d * RP;
            char* dl = smem + 102400 + sb * 5120 + d * RP;
#pragma unroll
            for (int j = 0; j < 32; j++) {
                float f = src[(size_t)j * D3];
                __nv_bfloat16 hi_ = __float2bfloat16(f);
                __nv_bfloat16 lo_ = __float2bfloat16(f - __bfloat162float(hi_));
                *(uint16_t*)(dh + j * 2) = __bfloat16_as_ushort(hi_);
                *(uint16_t*)(dl + j * 2) = __bfloat16_as_ushort(lo_);
            }
        }
        __syncthreads();

        // ---- S = Q K^T (3-pass hi/lo) ----
        float S[16][4];
#pragma unroll
        for (int ni = 0; ni < 16; ni++)
#pragma unroll
            for (int j = 0; j < 4; j++) S[ni][j] = 0.f;

#pragma unroll
        for (int kc = 0; kc < 4; kc++) {
            const int cc = kc >> 1;
            const int ks = (kc & 1) * 16;
            const char* Ah = smem + cc * 10240 + (w * 16 + r) * RP + (ks + 2 * q) * 2;
            const char* Al = Ah + 20480;
            uint32_t aH[4], aL[4];
            aH[0] = *(const uint32_t*)(Ah);
            aH[1] = *(const uint32_t*)(Ah + 8 * RP);
            aH[2] = *(const uint32_t*)(Ah + 16);
            aH[3] = *(const uint32_t*)(Ah + 8 * RP + 16);
            aL[0] = *(const uint32_t*)(Al);
            aL[1] = *(const uint32_t*)(Al + 8 * RP);
            aL[2] = *(const uint32_t*)(Al + 16);
            aL[3] = *(const uint32_t*)(Al + 8 * RP + 16);
            const char* Bh = smem + 40960 + cc * 10240;
            const char* Bl = smem + 61440 + cc * 10240;
#pragma unroll
            for (int ni = 0; ni < 16; ni += 2) {
                const uint32_t o0 = (uint32_t)(ni * 8 + r) * RP + (ks + 2 * q) * 2;
                const uint32_t o1 = (uint32_t)((ni + 1) * 8 + r) * RP + (ks + 2 * q) * 2;
                uint32_t bh0[2] = {*(const uint32_t*)(Bh + o0), *(const uint32_t*)(Bh + o0 + 16)};
                uint32_t bh1[2] = {*(const uint32_t*)(Bh + o1), *(const uint32_t*)(Bh + o1 + 16)};
                uint32_t bl0[2] = {*(const uint32_t*)(Bl + o0), *(const uint32_t*)(Bl + o0 + 16)};
                uint32_t bl1[2] = {*(const uint32_t*)(Bl + o1), *(const uint32_t*)(Bl + o1 + 16)};
                mma16816(S[ni], aH, bh0);     mma16816(S[ni + 1], aH, bh1);
                mma16816(S[ni], aH, bl0);     mma16816(S[ni + 1], aH, bl1);
                mma16816(S[ni], aL, bh0);     mma16816(S[ni + 1], aL, bh1);
            }
        }

        // ---- causal mask on diagonal tile ----
        if (kt == qt) {
            const int row0 = w * 16 + r;
#pragma unroll
            for (int ni = 0; ni < 16; ni++) {
                const int c0 = ni * 8 + 2 * q;
                if (c0 > row0)     S[ni][0] = -1e30f;
                if (c0 + 1 > row0) S[ni][1] = -1e30f;
                if (c0 > row0 + 8)     S[ni][2] = -1e30f;
                if (c0 + 1 > row0 + 8) S[ni][3] = -1e30f;
            }
        }

        // ---- online softmax ----
        float mx0 = -1e30f, mx1 = -1e30f;
#pragma unroll
        for (int ni = 0; ni < 16; ni++) {
            mx0 = fmaxf(mx0, fmaxf(S[ni][0], S[ni][1]));
            mx1 = fmaxf(mx1, fmaxf(S[ni][2], S[ni][3]));
        }
        mx0 = fmaxf(mx0, __shfl_xor_sync(0xffffffffu, mx0, 1));
        mx0 = fmaxf(mx0, __shfl_xor_sync(0xffffffffu, mx0, 2));
        mx1 = fmaxf(mx1, __shfl_xor_sync(0xffffffffu, mx1, 1));
        mx1 = fmaxf(mx1, __shfl_xor_sync(0xffffffffu, mx1, 2));
        const float mn0 = fmaxf(m0, mx0);
        const float mn1 = fmaxf(m1, mx1);
        const float a0 = __expf(m0 - mn0);
        const float a1 = __expf(m1 - mn1);
        m0 = mn0; m1 = mn1;
#pragma unroll
        for (int ni = 0; ni < 8; ni++) {
            Oacc[ni][0] *= a0; Oacc[ni][1] *= a0;
            Oacc[ni][2] *= a1; Oacc[ni][3] *= a1;
        }
        float s0 = 0.f, s1 = 0.f;
#pragma unroll
        for (int ni = 0; ni < 16; ni++) {
            S[ni][0] = __expf(S[ni][0] - m0);
            S[ni][1] = __expf(S[ni][1] - m0);
            S[ni][2] = __expf(S[ni][2] - m1);
            S[ni][3] = __expf(S[ni][3] - m1);
            s0 += S[ni][0] + S[ni][1];
            s1 += S[ni][2] + S[ni][3];
        }
        s0 += __shfl_xor_sync(0xffffffffu, s0, 1);
        s0 += __shfl_xor_sync(0xffffffffu, s0, 2);
        s1 += __shfl_xor_sync(0xffffffffu, s1, 1);
        s1 += __shfl_xor_sync(0xffffffffu, s1, 2);
        l0 = l0 * a0 + s0;
        l1 = l1 * a1 + s1;

        // ---- O += P @ V ----
#pragma unroll
        for (int kc = 0; kc < 8; kc++) {
            uint32_t aH[4], aL[4];
            aH[0] = packpair(S[2 * kc][0],     S[2 * kc][1],     aL[0]);
            aH[1] = packpair(S[2 * kc][2],     S[2 * kc][3],     aL[1]);
            aH[2] = packpair(S[2 * kc + 1][0], S[2 * kc + 1][1], aL[2]);
            aH[3] = packpair(S[2 * kc + 1][2], S[2 * kc + 1][3], aL[3]);
            const int cc = kc >> 1;
            const int ks = (kc & 1) * 16;
            const char* Bh = smem + 81920 + cc * 5120;
            const char* Bl = smem + 102400 + cc * 5120;
#pragma unroll
            for (int ni = 0; ni < 8; ni += 2) {
                const uint32_t o0 = (uint32_t)(ni * 8 + r) * RP + (ks + 2 * q) * 2;
                const uint32_t o1 = (uint32_t)((ni + 1) * 8 + r) * RP + (ks + 2 * q) * 2;
                uint32_t bh0[2] = {*(const uint32_t*)(Bh + o0), *(const uint32_t*)(Bh + o0 + 16)};
                uint32_t bh1[2] = {*(const uint32_t*)(Bh + o1), *(const uint32_t*)(Bh + o1 + 16)};
                uint32_t bl0[2] = {*(const uint32_t*)(Bl + o0), *(const uint32_t*)(Bl + o0 + 16)};
                uint32_t bl1[2] = {*(const uint32_t*)(Bl + o1), *(const uint32_t*)(Bl + o1 + 16)};
                mma16816(Oacc[ni], aH, bh0);     mma16816(Oacc[ni + 1], aH, bh1);
                mma16816(Oacc[ni], aH, bl0);     mma16816(Oacc[ni + 1], aH, bl1);
                mma16816(Oacc[ni], aL, bh0);     mma16816(Oacc[ni + 1], aL, bh1);
            }
        }
    }

    const float inv0 = 1.f / l0;
    const float inv1 = 1.f / l1;
    const int rowg = qt * 128 + w * 16 + r;
    float* O0 = ctx + ((size_t)b * SS + rowg) * DD + h * DH;
    float* O1 = O0 + (size_t)8 * DD;
#pragma unroll
    for (int ni = 0; ni < 8; ni++) {
        const int col = ni * 8 + 2 * q;
        *(float2*)(O0 + col) = make_float2(Oacc[ni][0] * inv0, Oacc[ni][1] * inv0);
        *(float2*)(O1 + col) = make_float2(Oacc[ni][2] * inv1, Oacc[ni][3] * inv1);
    }
}

// ---------------- LayerNorm over D=1024 -----------------------------------
__global__ __launch_bounds__(256) void layernorm_k(
    const float* __restrict__ x, const float* __restrict__ w,
    const float* __restrict__ b, float* __restrict__ out)
{
    const size_t row = blockIdx.x;
    const float* px = x + row * DD;
    float* po = out + row * DD;
    const int tid = threadIdx.x;

    float4 v = *(const float4*)(px + tid * 4);
    float s = v.x + v.y + v.z + v.w;
    float sq = v.x * v.x + v.y * v.y + v.z * v.z + v.w * v.w;

    __shared__ float rs[256];
    __shared__ float rq[256];
    rs[tid] = s;
    rq[tid] = sq;
    __syncthreads();
    for (int st = 128; st > 0; st >>= 1) {
        if (tid < st) { rs[tid] += rs[tid + st]; rq[tid] += rq[tid + st]; }
        __syncthreads();
    }
    const float mean = rs[0] * (1.f / DD);
    const float var = rq[0] * (1.f / DD) - mean * mean;
    const float rstd = rsqrtf(var + 1e-5f);

    float4 wv = *(const float4*)(w + tid * 4);
    float4 bv = *(const float4*)(b + tid * 4);
    float4 o;
    o.x = (v.x - mean) * rstd * wv.x + bv.x;
    o.y = (v.y - mean) * rstd * wv.y + bv.y;
    o.z = (v.z - mean) * rstd * wv.z + bv.z;
    o.w = (v.w - mean) * rstd * wv.w + bv.w;
    *(float4*)(po + tid * 4) = o;
}

// --------------------------------- driver ---------------------------------
extern "C" void kernel_launch(void* const* d_in, const int* in_sizes, int n_in,
                              void* d_out, int out_size)
{
    (void)in_sizes; (void)n_in; (void)out_size;
    const float* x     = (const float*)d_in[0];
    const float* qkv_w = (const float*)d_in[1];
    const float* qkv_b = (const float*)d_in[2];
    const float* out_w = (const float*)d_in[3];
    const float* out_b = (const float*)d_in[4];
    const float* w1    = (const float*)d_in[5];
    const float* b1    = (const float*)d_in[6];
    const float* w2    = (const float*)d_in[7];
    const float* b2    = (const float*)d_in[8];
    const float* ln1w  = (const float*)d_in[9];
    const float* ln1b  = (const float*)d_in[10];
    const float* ln2w  = (const float*)d_in[11];
    const float* ln2b  = (const float*)d_in[12];
    float* out = (float*)d_out;

    float *h, *qkv, *ctx, *tmp, *mlp;
    cudaGetSymbolAddress((void**)&h, g_h);
    cudaGetSymbolAddress((void**)&qkv, g_qkv);
    cudaGetSymbolAddress((void**)&ctx, g_ctx);
    cudaGetSymbolAddress((void**)&tmp, g_tmp);
    cudaGetSymbolAddress((void**)&mlp, g_mlp);

    cudaFuncSetAttribute(tgemm<0>, cudaFuncAttributeMaxDynamicSharedMemorySize, TG_SMEM);
    cudaFuncSetAttribute(tgemm<1>, cudaFuncAttributeMaxDynamicSharedMemorySize, TG_SMEM);
    cudaFuncSetAttribute(tgemm<2>, cudaFuncAttributeMaxDynamicSharedMemorySize, TG_SMEM);
    cudaFuncSetAttribute(flash_attn, cudaFuncAttributeMaxDynamicSharedMemorySize, FA_SMEM);

    const size_t act_bytes = (size_t)BB * SS * DD * sizeof(float);
    cudaMemcpyAsync(h, x, act_bytes, cudaMemcpyDeviceToDevice);

    const int M = BB * SS;

    for (int l = 0; l < NL; l++) {
        const float* lqw = qkv_w + (size_t)l * D3 * DD;
        const float* lqb = qkv_b + (size_t)l * D3;
        const float* low = out_w + (size_t)l * DD * DD;
        const float* lob = out_b + (size_t)l * DD;
        const float* lw1 = w1 + (size_t)l * DFF * DD;
        const float* lb1 = b1 + (size_t)l * DFF;
        const float* lw2 = w2 + (size_t)l * DD * DFF;
        const float* lb2 = b2 + (size_t)l * DD;

        tgemm<0><<<dim3(D3 / 64, M / 128), 128, TG_SMEM>>>(
            h, DD, lqw, DD, lqb, nullptr, 0, qkv, D3, DD);

        flash_attn<<<dim3(SS / 128, BB * NH), 256, FA_SMEM>>>(qkv, ctx);

        tgemm<2><<<dim3(DD / 64, M / 128), 128, TG_SMEM>>>(
            ctx, DD, low, DD, lob, h, DD, tmp, DD, DD);
        layernorm_k<<<M, 256>>>(tmp, ln1w + (size_t)l * DD, ln1b + (size_t)l * DD, h);

        tgemm<1><<<dim3(DFF / 64, M / 128), 128, TG_SMEM>>>(
            h, DD, lw1, DD, lb1, nullptr, 0, mlp, DFF, DD);

        tgemm<2><<<dim3(DD / 64, M / 128), 128, TG_SMEM>>>(
            mlp, DFF, lw2, DFF, lb2, h, DD, tmp, DD, DFF);
        layernorm_k<<<M, 256>>>(tmp, ln2w + (size_t)l * DD, ln2b + (size_t)l * DD, h);
    }

    cudaMemcpyAsync(out, h, act_bytes, cudaMemcpyDeviceToDevice);
}

// round 16
// speedup vs baseline: 1.2565x; 1.2565x over previous
#include <cuda_runtime.h>
#include <cuda_bf16.h>
#include <math.h>
#include <stdint.h>

#define BB 4
#define SS 1024
#define DD 1024
#define D3 3072
#define DFF 4096
#define NH 16
#define DH 64
#define NL 16

__device__ float g_h[(size_t)BB * SS * DD];
__device__ float g_qkv[(size_t)BB * SS * D3];
__device__ float g_ctx[(size_t)BB * SS * DD];
__device__ float g_tmp[(size_t)BB * SS * DD];
__device__ float g_mlp[(size_t)BB * SS * DFF];

// =================== bf16 hi/lo split helpers =============================
__device__ __forceinline__ void cvt_hilo4(float4 v, uint32_t& h01, uint32_t& h23,
                                          uint32_t& l01, uint32_t& l23) {
    __nv_bfloat16 hx = __float2bfloat16(v.x);
    __nv_bfloat16 hy = __float2bfloat16(v.y);
    __nv_bfloat16 hz = __float2bfloat16(v.z);
    __nv_bfloat16 hw = __float2bfloat16(v.w);
    __nv_bfloat16 lx = __float2bfloat16(v.x - __bfloat162float(hx));
    __nv_bfloat16 ly = __float2bfloat16(v.y - __bfloat162float(hy));
    __nv_bfloat16 lz = __float2bfloat16(v.z - __bfloat162float(hz));
    __nv_bfloat16 lw = __float2bfloat16(v.w - __bfloat162float(hw));
    h01 = ((uint32_t)__bfloat16_as_ushort(hy) << 16) | __bfloat16_as_ushort(hx);
    h23 = ((uint32_t)__bfloat16_as_ushort(hw) << 16) | __bfloat16_as_ushort(hz);
    l01 = ((uint32_t)__bfloat16_as_ushort(ly) << 16) | __bfloat16_as_ushort(lx);
    l23 = ((uint32_t)__bfloat16_as_ushort(lw) << 16) | __bfloat16_as_ushort(lz);
}

__device__ __forceinline__ uint32_t packpair(float x, float y, uint32_t& lo) {
    __nv_bfloat16 hx = __float2bfloat16(x);
    __nv_bfloat16 hy = __float2bfloat16(y);
    __nv_bfloat16 lx = __float2bfloat16(x - __bfloat162float(hx));
    __nv_bfloat16 ly = __float2bfloat16(y - __bfloat162float(hy));
    lo = ((uint32_t)__bfloat16_as_ushort(ly) << 16) | __bfloat16_as_ushort(lx);
    return ((uint32_t)__bfloat16_as_ushort(hy) << 16) | __bfloat16_as_ushort(hx);
}

__device__ __forceinline__ void mma16816(float* c, const uint32_t* a, const uint32_t* b) {
    asm volatile(
        "mma.sync.aligned.m16n8k16.row.col.f32.bf16.bf16.f32 "
        "{%0,%1,%2,%3},{%4,%5,%6,%7},{%8,%9},{%0,%1,%2,%3};"
        : "+f"(c[0]), "+f"(c[1]), "+f"(c[2]), "+f"(c[3])
        : "r"(a[0]), "r"(a[1]), "r"(a[2]), "r"(a[3]), "r"(b[0]), "r"(b[1]));
}

// ============== tensor-core GEMM: C = A[M,K] @ W[N,K]^T + bias =============
// bf16 hi/lo 3-MMA via mma.sync. Block 128x128, 8 warps (warp 32x64),
// K chunk 32, register-prefetch double-buffered. (round-5 proven optimum)
#define TG_BUF  40960
#define TG_SMEM (2 * TG_BUF)
#define RP      80   // row pitch in bytes - conflict-free

template <int EPI>
__global__ __launch_bounds__(256, 1) void tgemm(
    const float* __restrict__ A, int lda,
    const float* __restrict__ W, int ldw,
    const float* __restrict__ bias,
    const float* __restrict__ R, int ldr,
    float* __restrict__ C, int ldc,
    int K)
{
    extern __shared__ __align__(16) char smem[];
    const int tid = threadIdx.x;
    const int lane = tid & 31;
    const int wid = tid >> 5;
    const int wm = wid >> 1;
    const int wn = wid & 1;
    const int row0 = blockIdx.y * 128;
    const int col0 = blockIdx.x * 128;

    const int srow = tid >> 1;
    const int kb = (tid & 1) * 16;
    const float* Ag = A + (size_t)(row0 + srow) * lda + kb;
    const float* Wg = W + (size_t)(col0 + srow) * ldw + kb;

    float4 Areg[4], Breg[4];
    const int nc = K >> 5;

#pragma unroll
    for (int i = 0; i < 4; i++) {
        Areg[i] = *(const float4*)(Ag + i * 4);
        Breg[i] = *(const float4*)(Wg + i * 4);
    }
    {
        char* bb = smem;
        const uint32_t off0 = (uint32_t)srow * RP + (uint32_t)kb * 2;
#pragma unroll
        for (int i = 0; i < 4; i++) {
            uint32_t h01, h23, l01, l23;
            cvt_hilo4(Areg[i], h01, h23, l01, l23);
            const uint32_t o = off0 + i * 8;
            *(uint32_t*)(bb + o) = h01;
            *(uint32_t*)(bb + o + 4) = h23;
            *(uint32_t*)(bb + 10240 + o) = l01;
            *(uint32_t*)(bb + 10240 + o + 4) = l23;
            cvt_hilo4(Breg[i], h01, h23, l01, l23);
            *(uint32_t*)(bb + 20480 + o) = h01;
            *(uint32_t*)(bb + 20480 + o + 4) = h23;
            *(uint32_t*)(bb + 30720 + o) = l01;
            *(uint32_t*)(bb + 30720 + o + 4) = l23;
        }
    }
    __syncthreads();

    float acc[2][8][4];
#pragma unroll
    for (int mi = 0; mi < 2; mi++)
#pragma unroll
        for (int ni = 0; ni < 8; ni++)
#pragma unroll
            for (int j = 0; j < 4; j++) acc[mi][ni][j] = 0.f;

    const int r = lane >> 2;
    const int q = lane & 3;

    for (int c = 0; c < nc; c++) {
        if (c + 1 < nc) {
            const int k0 = (c + 1) << 5;
#pragma unroll
            for (int i = 0; i < 4; i++) {
                Areg[i] = *(const float4*)(Ag + k0 + i * 4);
                Breg[i] = *(const float4*)(Wg + k0 + i * 4);
            }
        }

        const char* bb = smem + (c & 1) * TG_BUF;
#pragma unroll
        for (int ks = 0; ks < 32; ks += 16) {
            uint32_t aH[2][4], aL[2][4];
#pragma unroll
            for (int mi = 0; mi < 2; mi++) {
                const uint32_t row = (uint32_t)(wm * 32 + mi * 16 + r);
                const uint32_t o = row * RP + (uint32_t)(ks + 2 * q) * 2;
                aH[mi][0] = *(const uint32_t*)(bb + o);
                aH[mi][1] = *(const uint32_t*)(bb + o + 8 * RP);
                aH[mi][2] = *(const uint32_t*)(bb + o + 16);
                aH[mi][3] = *(const uint32_t*)(bb + o + 8 * RP + 16);
                aL[mi][0] = *(const uint32_t*)(bb + 10240 + o);
                aL[mi][1] = *(const uint32_t*)(bb + 10240 + o + 8 * RP);
                aL[mi][2] = *(const uint32_t*)(bb + 10240 + o + 16);
                aL[mi][3] = *(const uint32_t*)(bb + 10240 + o + 8 * RP + 16);
            }
            uint32_t bH[8][2], bL[8][2];
#pragma unroll
            for (int ni = 0; ni < 8; ni++) {
                const uint32_t n = (uint32_t)(wn * 64 + ni * 8 + r);
                const uint32_t o = n * RP + (uint32_t)(ks + 2 * q) * 2;
                bH[ni][0] = *(const uint32_t*)(bb + 20480 + o);
                bH[ni][1] = *(const uint32_t*)(bb + 20480 + o + 16);
                bL[ni][0] = *(const uint32_t*)(bb + 30720 + o);
                bL[ni][1] = *(const uint32_t*)(bb + 30720 + o + 16);
            }
#pragma unroll
            for (int mi = 0; mi < 2; mi++)
#pragma unroll
                for (int ni = 0; ni < 8; ni++) {
                    mma16816(acc[mi][ni], aH[mi], bH[ni]);
                    mma16816(acc[mi][ni], aH[mi], bL[ni]);
                    mma16816(acc[mi][ni], aL[mi], bH[ni]);
                }
        }

        if (c + 1 < nc) {
            char* wb = smem + ((c + 1) & 1) * TG_BUF;
            const uint32_t off0 = (uint32_t)srow * RP + (uint32_t)kb * 2;
#pragma unroll
            for (int i = 0; i < 4; i++) {
                uint32_t h01, h23, l01, l23;
                cvt_hilo4(Areg[i], h01, h23, l01, l23);
                const uint32_t o = off0 + i * 8;
                *(uint32_t*)(wb + o) = h01;
                *(uint32_t*)(wb + o + 4) = h23;
                *(uint32_t*)(wb + 10240 + o) = l01;
                *(uint32_t*)(wb + 10240 + o + 4) = l23;
                cvt_hilo4(Breg[i], h01, h23, l01, l23);
                *(uint32_t*)(wb + 20480 + o) = h01;
                *(uint32_t*)(wb + 20480 + o + 4) = h23;
                *(uint32_t*)(wb + 30720 + o) = l01;
                *(uint32_t*)(wb + 30720 + o + 4) = l23;
            }
            __syncthreads();
        }
    }

#pragma unroll
    for (int mi = 0; mi < 2; mi++) {
        const int rbase = row0 + wm * 32 + mi * 16 + r;
#pragma unroll
        for (int ni = 0; ni < 8; ni++) {
            const int col = col0 + wn * 64 + ni * 8 + 2 * q;
            float2 bv = *(const float2*)(bias + col);
            float o0 = acc[mi][ni][0] + bv.x;
            float o1 = acc[mi][ni][1] + bv.y;
            float o2 = acc[mi][ni][2] + bv.x;
            float o3 = acc[mi][ni][3] + bv.y;
            if (EPI == 1) {
                o0 = fmaxf(o0, 0.f); o1 = fmaxf(o1, 0.f);
                o2 = fmaxf(o2, 0.f); o3 = fmaxf(o3, 0.f);
            }
            if (EPI == 2) {
                float2 r0 = *(const float2*)(R + (size_t)rbase * ldr + col);
                float2 r1 = *(const float2*)(R + (size_t)(rbase + 8) * ldr + col);
                o0 += r0.x; o1 += r0.y; o2 += r1.x; o3 += r1.y;
            }
            *(float2*)(C + (size_t)rbase * ldc + col) = make_float2(o0, o1);
            *(float2*)(C + (size_t)(rbase + 8) * ldc + col) = make_float2(o2, o3);
        }
    }
}

// ====================== fused flash attention (HMMA) ======================
// Round-5 base + Q-frags-in-registers + wide V stores + diagonal MMA skip.
// QH 0 / QL 20480 / KH 40960 / KL 61440 / VH 81920 / VL 102400 -> 122880 B.
#define FA_SMEM 122880

__global__ __launch_bounds__(256, 1) void flash_attn(
    const float* __restrict__ qkv, float* __restrict__ ctx)
{
    extern __shared__ __align__(16) char smem[];
    const int tid = threadIdx.x;
    const int lane = tid & 31;
    const int w = tid >> 5;
    const int r = lane >> 2;
    const int q = lane & 3;
    const int bh = blockIdx.y;
    const int b = bh >> 4;
    const int h = bh & 15;
    const int qt = gridDim.x - 1 - blockIdx.x;  // long blocks first

    const float* Qg = qkv + (size_t)b * SS * D3 + h * DH;
    const float* Kg = Qg + DD;
    const float* Vg = Qg + 2 * DD;

    // ---- load Q tile once (scaled by 1/8), hi/lo split ----
    {
        const int srow = tid >> 1;
        const int c = tid & 1;
        const float* src = Qg + (size_t)(qt * 128 + srow) * D3 + c * 32;
        char* dh = smem + c * 10240 + srow * RP;
        char* dl = smem + 20480 + c * 10240 + srow * RP;
#pragma unroll
        for (int i = 0; i < 8; i++) {
            float4 v = *(const float4*)(src + i * 4);
            v.x *= 0.125f; v.y *= 0.125f; v.z *= 0.125f; v.w *= 0.125f;
            uint32_t h01, h23, l01, l23;
            cvt_hilo4(v, h01, h23, l01, l23);
            *(uint32_t*)(dh + i * 8) = h01;
            *(uint32_t*)(dh + i * 8 + 4) = h23;
            *(uint32_t*)(dl + i * 8) = l01;
            *(uint32_t*)(dl + i * 8 + 4) = l23;
        }
    }
    __syncthreads();

    // ---- hoist Q fragments into registers (read once, reused all tiles) ----
    uint32_t Qh[4][4], Ql[4][4];
#pragma unroll
    for (int kc = 0; kc < 4; kc++) {
        const int cc = kc >> 1;
        const int ks = (kc & 1) * 16;
        const char* Ah = smem + cc * 10240 + (w * 16 + r) * RP + (ks + 2 * q) * 2;
        const char* Al = Ah + 20480;
        Qh[kc][0] = *(const uint32_t*)(Ah);
        Qh[kc][1] = *(const uint32_t*)(Ah + 8 * RP);
        Qh[kc][2] = *(const uint32_t*)(Ah + 16);
        Qh[kc][3] = *(const uint32_t*)(Ah + 8 * RP + 16);
        Ql[kc][0] = *(const uint32_t*)(Al);
        Ql[kc][1] = *(const uint32_t*)(Al + 8 * RP);
        Ql[kc][2] = *(const uint32_t*)(Al + 16);
        Ql[kc][3] = *(const uint32_t*)(Al + 8 * RP + 16);
    }

    float Oacc[8][4];
#pragma unroll
    for (int ni = 0; ni < 8; ni++)
#pragma unroll
        for (int j = 0; j < 4; j++) Oacc[ni][j] = 0.f;
    float m0 = -1e30f, m1 = -1e30f, l0 = 0.f, l1 = 0.f;

    for (int kt = 0; kt <= qt; kt++) {
        __syncthreads();
        // ---- K tile (hi/lo) ----
        {
            const int srow = tid >> 1;
            const int c = tid & 1;
            const float* src = Kg + (size_t)(kt * 128 + srow) * D3 + c * 32;
            char* dh = smem + 40960 + c * 10240 + srow * RP;
            char* dl = smem + 61440 + c * 10240 + srow * RP;
#pragma unroll
            for (int i = 0; i < 8; i++) {
                float4 v = *(const float4*)(src + i * 4);
                uint32_t h01, h23, l01, l23;
                cvt_hilo4(v, h01, h23, l01, l23);
                *(uint32_t*)(dh + i * 8) = h01;
                *(uint32_t*)(dh + i * 8 + 4) = h23;
                *(uint32_t*)(dl + i * 8) = l01;
                *(uint32_t*)(dl + i * 8 + 4) = l23;
            }
        }
        // ---- V tile transposed: Vs[d][s] hi/lo, wide (paired) stores ----
        {
            const int d = tid & 63;
            const int sb = tid >> 6;
            const float* src = Vg + (size_t)(kt * 128 + sb * 32) * D3 + d;
            char* dh = smem + 81920 + sb * 5120 + d * RP;
            char* dl = smem + 102400 + sb * 5120 + d * RP;
#pragma unroll
            for (int j = 0; j < 32; j += 2) {
                float f0 = src[(size_t)j * D3];
                float f1 = src[(size_t)(j + 1) * D3];
                uint32_t lo;
                uint32_t hi = packpair(f0, f1, lo);
                *(uint32_t*)(dh + j * 2) = hi;
                *(uint32_t*)(dl + j * 2) = lo;
            }
        }
        __syncthreads();

        // ---- S = Q K^T (3-pass hi/lo); skip fully-masked frags on diag ----
        float S[16][4];
#pragma unroll
        for (int ni = 0; ni < 16; ni++)
#pragma unroll
            for (int j = 0; j < 4; j++) S[ni][j] = 0.f;

        const bool diag = (kt == qt);
        const int rowmax = w * 16 + 15;   // max local q-row this warp owns

#pragma unroll
        for (int kc = 0; kc < 4; kc++) {
            const int cc = kc >> 1;
            const int ks = (kc & 1) * 16;
            const char* Bh = smem + 40960 + cc * 10240;
            const char* Bl = smem + 61440 + cc * 10240;
#pragma unroll
            for (int ni = 0; ni < 16; ni += 2) {
                if (diag && ni * 8 > rowmax) break;  // whole frag pair masked
                const uint32_t o0 = (uint32_t)(ni * 8 + r) * RP + (ks + 2 * q) * 2;
                const uint32_t o1 = (uint32_t)((ni + 1) * 8 + r) * RP + (ks + 2 * q) * 2;
                uint32_t bh0[2] = {*(const uint32_t*)(Bh + o0), *(const uint32_t*)(Bh + o0 + 16)};
                uint32_t bh1[2] = {*(const uint32_t*)(Bh + o1), *(const uint32_t*)(Bh + o1 + 16)};
                uint32_t bl0[2] = {*(const uint32_t*)(Bl + o0), *(const uint32_t*)(Bl + o0 + 16)};
                uint32_t bl1[2] = {*(const uint32_t*)(Bl + o1), *(const uint32_t*)(Bl + o1 + 16)};
                mma16816(S[ni], Qh[kc], bh0);     mma16816(S[ni + 1], Qh[kc], bh1);
                mma16816(S[ni], Qh[kc], bl0);     mma16816(S[ni + 1], Qh[kc], bl1);
                mma16816(S[ni], Ql[kc], bh0);     mma16816(S[ni + 1], Ql[kc], bh1);
            }
        }

        // ---- causal mask on diagonal tile ----
        if (diag) {
            const int row0 = w * 16 + r;
#pragma unroll
            for (int ni = 0; ni < 16; ni++) {
                const int c0 = ni * 8 + 2 * q;
                if (c0 > row0)     S[ni][0] = -1e30f;
                if (c0 + 1 > row0) S[ni][1] = -1e30f;
                if (c0 > row0 + 8)     S[ni][2] = -1e30f;
                if (c0 + 1 > row0 + 8) S[ni][3] = -1e30f;
            }
        }

        // ---- online softmax ----
        float mx0 = -1e30f, mx1 = -1e30f;
#pragma unroll
        for (int ni = 0; ni < 16; ni++) {
            mx0 = fmaxf(mx0, fmaxf(S[ni][0], S[ni][1]));
            mx1 = fmaxf(mx1, fmaxf(S[ni][2], S[ni][3]));
        }
        mx0 = fmaxf(mx0, __shfl_xor_sync(0xffffffffu, mx0, 1));
        mx0 = fmaxf(mx0, __shfl_xor_sync(0xffffffffu, mx0, 2));
        mx1 = fmaxf(mx1, __shfl_xor_sync(0xffffffffu, mx1, 1));
        mx1 = fmaxf(mx1, __shfl_xor_sync(0xffffffffu, mx1, 2));
        const float mn0 = fmaxf(m0, mx0);
        const float mn1 = fmaxf(m1, mx1);
        const float a0 = __expf(m0 - mn0);
        const float a1 = __expf(m1 - mn1);
        m0 = mn0; m1 = mn1;
#pragma unroll
        for (int ni = 0; ni < 8; ni++) {
            Oacc[ni][0] *= a0; Oacc[ni][1] *= a0;
            Oacc[ni][2] *= a1; Oacc[ni][3] *= a1;
        }
        float s0 = 0.f, s1 = 0.f;
#pragma unroll
        for (int ni = 0; ni < 16; ni++) {
            S[ni][0] = __expf(S[ni][0] - m0);
            S[ni][1] = __expf(S[ni][1] - m0);
            S[ni][2] = __expf(S[ni][2] - m1);
            S[ni][3] = __expf(S[ni][3] - m1);
            s0 += S[ni][0] + S[ni][1];
            s1 += S[ni][2] + S[ni][3];
        }
        s0 += __shfl_xor_sync(0xffffffffu, s0, 1);
        s0 += __shfl_xor_sync(0xffffffffu, s0, 2);
        s1 += __shfl_xor_sync(0xffffffffu, s1, 1);
        s1 += __shfl_xor_sync(0xffffffffu, s1, 2);
        l0 = l0 * a0 + s0;
        l1 = l1 * a1 + s1;

        // ---- O += P @ V; on diag tile skip kc blocks where P == 0 ----
#pragma unroll
        for (int kc = 0; kc < 8; kc++) {
            if (diag && kc * 16 > rowmax) break;  // all P in block are zero
            uint32_t aH[4], aL[4];
            aH[0] = packpair(S[2 * kc][0],     S[2 * kc][1],     aL[0]);
            aH[1] = packpair(S[2 * kc][2],     S[2 * kc][3],     aL[1]);
            aH[2] = packpair(S[2 * kc + 1][0], S[2 * kc + 1][1], aL[2]);
            aH[3] = packpair(S[2 * kc + 1][2], S[2 * kc + 1][3], aL[3]);
            const int cc = kc >> 1;
            const int ks = (kc & 1) * 16;
            const char* Bh = smem + 81920 + cc * 5120;
            const char* Bl = smem + 102400 + cc * 5120;
#pragma unroll
            for (int ni = 0; ni < 8; ni += 2) {
                const uint32_t o0 = (uint32_t)(ni * 8 + r) * RP + (ks + 2 * q) * 2;
                const uint32_t o1 = (uint32_t)((ni + 1) * 8 + r) * RP + (ks + 2 * q) * 2;
                uint32_t bh0[2] = {*(const uint32_t*)(Bh + o0), *(const uint32_t*)(Bh + o0 + 16)};
                uint32_t bh1[2] = {*(const uint32_t*)(Bh + o1), *(const uint32_t*)(Bh + o1 + 16)};
                uint32_t bl0[2] = {*(const uint32_t*)(Bl + o0), *(const uint32_t*)(Bl + o0 + 16)};
                uint32_t bl1[2] = {*(const uint32_t*)(Bl + o1), *(const uint32_t*)(Bl + o1 + 16)};
                mma16816(Oacc[ni], aH, bh0);     mma16816(Oacc[ni + 1], aH, bh1);
                mma16816(Oacc[ni], aH, bl0);     mma16816(Oacc[ni + 1], aH, bl1);
                mma16816(Oacc[ni], aL, bh0);     mma16816(Oacc[ni + 1], aL, bh1);
            }
        }
    }

    const float inv0 = 1.f / l0;
    const float inv1 = 1.f / l1;
    const int rowg = qt * 128 + w * 16 + r;
    float* O0 = ctx + ((size_t)b * SS + rowg) * DD + h * DH;
    float* O1 = O0 + (size_t)8 * DD;
#pragma unroll
    for (int ni = 0; ni < 8; ni++) {
        const int col = ni * 8 + 2 * q;
        *(float2*)(O0 + col) = make_float2(Oacc[ni][0] * inv0, Oacc[ni][1] * inv0);
        *(float2*)(O1 + col) = make_float2(Oacc[ni][2] * inv1, Oacc[ni][3] * inv1);
    }
}

// ---------------- LayerNorm over D=1024 -----------------------------------
__global__ __launch_bounds__(256) void layernorm_k(
    const float* __restrict__ x, const float* __restrict__ w,
    const float* __restrict__ b, float* __restrict__ out)
{
    const size_t row = blockIdx.x;
    const float* px = x + row * DD;
    float* po = out + row * DD;
    const int tid = threadIdx.x;

    float4 v = *(const float4*)(px + tid * 4);
    float s = v.x + v.y + v.z + v.w;
    float sq = v.x * v.x + v.y * v.y + v.z * v.z + v.w * v.w;

    __shared__ float rs[256];
    __shared__ float rq[256];
    rs[tid] = s;
    rq[tid] = sq;
    __syncthreads();
    for (int st = 128; st > 0; st >>= 1) {
        if (tid < st) { rs[tid] += rs[tid + st]; rq[tid] += rq[tid + st]; }
        __syncthreads();
    }
    const float mean = rs[0] * (1.f / DD);
    const float var = rq[0] * (1.f / DD) - mean * mean;
    const float rstd = rsqrtf(var + 1e-5f);

    float4 wv = *(const float4*)(w + tid * 4);
    float4 bv = *(const float4*)(b + tid * 4);
    float4 o;
    o.x = (v.x - mean) * rstd * wv.x + bv.x;
    o.y = (v.y - mean) * rstd * wv.y + bv.y;
    o.z = (v.z - mean) * rstd * wv.z + bv.z;
    o.w = (v.w - mean) * rstd * wv.w + bv.w;
    *(float4*)(po + tid * 4) = o;
}

// --------------------------------- driver ---------------------------------
extern "C" void kernel_launch(void* const* d_in, const int* in_sizes, int n_in,
                              void* d_out, int out_size)
{
    (void)in_sizes; (void)n_in; (void)out_size;
    const float* x     = (const float*)d_in[0];
    const float* qkv_w = (const float*)d_in[1];
    const float* qkv_b = (const float*)d_in[2];
    const float* out_w = (const float*)d_in[3];
    const float* out_b = (const float*)d_in[4];
    const float* w1    = (const float*)d_in[5];
    const float* b1    = (const float*)d_in[6];
    const float* w2    = (const float*)d_in[7];
    const float* b2    = (const float*)d_in[8];
    const float* ln1w  = (const float*)d_in[9];
    const float* ln1b  = (const float*)d_in[10];
    const float* ln2w  = (const float*)d_in[11];
    const float* ln2b  = (const float*)d_in[12];
    float* out = (float*)d_out;

    float *h, *qkv, *ctx, *tmp, *mlp;
    cudaGetSymbolAddress((void**)&h, g_h);
    cudaGetSymbolAddress((void**)&qkv, g_qkv);
    cudaGetSymbolAddress((void**)&ctx, g_ctx);
    cudaGetSymbolAddress((void**)&tmp, g_tmp);
    cudaGetSymbolAddress((void**)&mlp, g_mlp);

    cudaFuncSetAttribute(tgemm<0>, cudaFuncAttributeMaxDynamicSharedMemorySize, TG_SMEM);
    cudaFuncSetAttribute(tgemm<1>, cudaFuncAttributeMaxDynamicSharedMemorySize, TG_SMEM);
    cudaFuncSetAttribute(tgemm<2>, cudaFuncAttributeMaxDynamicSharedMemorySize, TG_SMEM);
    cudaFuncSetAttribute(flash_attn, cudaFuncAttributeMaxDynamicSharedMemorySize, FA_SMEM);

    const size_t act_bytes = (size_t)BB * SS * DD * sizeof(float);
    cudaMemcpyAsync(h, x, act_bytes, cudaMemcpyDeviceToDevice);

    const int M = BB * SS;

    for (int l = 0; l < NL; l++) {
        const float* lqw = qkv_w + (size_t)l * D3 * DD;
        const float* lqb = qkv_b + (size_t)l * D3;
        const float* low = out_w + (size_t)l * DD * DD;
        const float* lob = out_b + (size_t)l * DD;
        const float* lw1 = w1 + (size_t)l * DFF * DD;
        const float* lb1 = b1 + (size_t)l * DFF;
        const float* lw2 = w2 + (size_t)l * DD * DFF;
        const float* lb2 = b2 + (size_t)l * DD;

        tgemm<0><<<dim3(D3 / 128, M / 128), 256, TG_SMEM>>>(
            h, DD, lqw, DD, lqb, nullptr, 0, qkv, D3, DD);

        flash_attn<<<dim3(SS / 128, BB * NH), 256, FA_SMEM>>>(qkv, ctx);

        tgemm<2><<<dim3(DD / 128, M / 128), 256, TG_SMEM>>>(
            ctx, DD, low, DD, lob, h, DD, tmp, DD, DD);
        layernorm_k<<<M, 256>>>(tmp, ln1w + (size_t)l * DD, ln1b + (size_t)l * DD, h);

        tgemm<1><<<dim3(DFF / 128, M / 128), 256, TG_SMEM>>>(
            h, DD, lw1, DD, lb1, nullptr, 0, mlp, DFF, DD);

        tgemm<2><<<dim3(DD / 128, M / 128), 256, TG_SMEM>>>(
            mlp, DFF, lw2, DFF, lb2, h, DD, tmp, DD, DFF);
        layernorm_k<<<M, 256>>>(tmp, ln2w + (size_t)l * DD, ln2b + (size_t)l * DD, h);
    }

    cudaMemcpyAsync(out, h, act_bytes, cudaMemcpyDeviceToDevice);
}

// round 17
// speedup vs baseline: 1.2696x; 1.0104x over previous
#include <cuda_runtime.h>
#include <cuda_bf16.h>
#include <math.h>
#include <stdint.h>

#define BB 4
#define SS 1024
#define DD 1024
#define D3 3072
#define DFF 4096
#define NH 16
#define DH 64
#define NL 16

__device__ float g_h[(size_t)BB * SS * DD];
__device__ float g_qkv[(size_t)BB * SS * D3];   // holds PACKED bf16 hi/lo words
__device__ float g_ctx[(size_t)BB * SS * DD];
__device__ float g_tmp[(size_t)BB * SS * DD];
__device__ float g_mlp[(size_t)BB * SS * DFF];

// =================== bf16 hi/lo split helpers =============================
__device__ __forceinline__ void cvt_hilo4(float4 v, uint32_t& h01, uint32_t& h23,
                                          uint32_t& l01, uint32_t& l23) {
    __nv_bfloat16 hx = __float2bfloat16(v.x);
    __nv_bfloat16 hy = __float2bfloat16(v.y);
    __nv_bfloat16 hz = __float2bfloat16(v.z);
    __nv_bfloat16 hw = __float2bfloat16(v.w);
    __nv_bfloat16 lx = __float2bfloat16(v.x - __bfloat162float(hx));
    __nv_bfloat16 ly = __float2bfloat16(v.y - __bfloat162float(hy));
    __nv_bfloat16 lz = __float2bfloat16(v.z - __bfloat162float(hz));
    __nv_bfloat16 lw = __float2bfloat16(v.w - __bfloat162float(hw));
    h01 = ((uint32_t)__bfloat16_as_ushort(hy) << 16) | __bfloat16_as_ushort(hx);
    h23 = ((uint32_t)__bfloat16_as_ushort(hw) << 16) | __bfloat16_as_ushort(hz);
    l01 = ((uint32_t)__bfloat16_as_ushort(ly) << 16) | __bfloat16_as_ushort(lx);
    l23 = ((uint32_t)__bfloat16_as_ushort(lw) << 16) | __bfloat16_as_ushort(lz);
}

__device__ __forceinline__ uint32_t packpair(float x, float y, uint32_t& lo) {
    __nv_bfloat16 hx = __float2bfloat16(x);
    __nv_bfloat16 hy = __float2bfloat16(y);
    __nv_bfloat16 lx = __float2bfloat16(x - __bfloat162float(hx));
    __nv_bfloat16 ly = __float2bfloat16(y - __bfloat162float(hy));
    lo = ((uint32_t)__bfloat16_as_ushort(ly) << 16) | __bfloat16_as_ushort(lx);
    return ((uint32_t)__bfloat16_as_ushort(hy) << 16) | __bfloat16_as_ushort(hx);
}

// pack one float into (hi16<<16)|lo16 word
__device__ __forceinline__ uint32_t pack_hilo(float x) {
    __nv_bfloat16 hi = __float2bfloat16(x);
    __nv_bfloat16 lo = __float2bfloat16(x - __bfloat162float(hi));
    return ((uint32_t)__bfloat16_as_ushort(hi) << 16) | __bfloat16_as_ushort(lo);
}

__device__ __forceinline__ void mma16816(float* c, const uint32_t* a, const uint32_t* b) {
    asm volatile(
        "mma.sync.aligned.m16n8k16.row.col.f32.bf16.bf16.f32 "
        "{%0,%1,%2,%3},{%4,%5,%6,%7},{%8,%9},{%0,%1,%2,%3};"
        : "+f"(c[0]), "+f"(c[1]), "+f"(c[2]), "+f"(c[3])
        : "r"(a[0]), "r"(a[1]), "r"(a[2]), "r"(a[3]), "r"(b[0]), "r"(b[1]));
}

// ============== tensor-core GEMM: C = A[M,K] @ W[N,K]^T + bias =============
// bf16 hi/lo 3-MMA via mma.sync. Block 128x128, 8 warps (warp 32x64),
// K chunk 32, register-prefetch double-buffered. (round-5 proven optimum)
// EPI: 0 = bias (fp32 out), 1 = bias+relu, 2 = bias+residual,
//      3 = bias + PACKED bf16 hi/lo output (for qkv -> flash)
#define TG_BUF  40960
#define TG_SMEM (2 * TG_BUF)
#define RP      80   // row pitch in bytes - conflict-free

template <int EPI>
__global__ __launch_bounds__(256, 1) void tgemm(
    const float* __restrict__ A, int lda,
    const float* __restrict__ W, int ldw,
    const float* __restrict__ bias,
    const float* __restrict__ R, int ldr,
    float* __restrict__ C, int ldc,
    int K)
{
    extern __shared__ __align__(16) char smem[];
    const int tid = threadIdx.x;
    const int lane = tid & 31;
    const int wid = tid >> 5;
    const int wm = wid >> 1;
    const int wn = wid & 1;
    const int row0 = blockIdx.y * 128;
    const int col0 = blockIdx.x * 128;

    const int srow = tid >> 1;
    const int kb = (tid & 1) * 16;
    const float* Ag = A + (size_t)(row0 + srow) * lda + kb;
    const float* Wg = W + (size_t)(col0 + srow) * ldw + kb;

    float4 Areg[4], Breg[4];
    const int nc = K >> 5;

#pragma unroll
    for (int i = 0; i < 4; i++) {
        Areg[i] = *(const float4*)(Ag + i * 4);
        Breg[i] = *(const float4*)(Wg + i * 4);
    }
    {
        char* bb = smem;
        const uint32_t off0 = (uint32_t)srow * RP + (uint32_t)kb * 2;
#pragma unroll
        for (int i = 0; i < 4; i++) {
            uint32_t h01, h23, l01, l23;
            cvt_hilo4(Areg[i], h01, h23, l01, l23);
            const uint32_t o = off0 + i * 8;
            *(uint32_t*)(bb + o) = h01;
            *(uint32_t*)(bb + o + 4) = h23;
            *(uint32_t*)(bb + 10240 + o) = l01;
            *(uint32_t*)(bb + 10240 + o + 4) = l23;
            cvt_hilo4(Breg[i], h01, h23, l01, l23);
            *(uint32_t*)(bb + 20480 + o) = h01;
            *(uint32_t*)(bb + 20480 + o + 4) = h23;
            *(uint32_t*)(bb + 30720 + o) = l01;
            *(uint32_t*)(bb + 30720 + o + 4) = l23;
        }
    }
    __syncthreads();

    float acc[2][8][4];
#pragma unroll
    for (int mi = 0; mi < 2; mi++)
#pragma unroll
        for (int ni = 0; ni < 8; ni++)
#pragma unroll
            for (int j = 0; j < 4; j++) acc[mi][ni][j] = 0.f;

    const int r = lane >> 2;
    const int q = lane & 3;

    for (int c = 0; c < nc; c++) {
        if (c + 1 < nc) {
            const int k0 = (c + 1) << 5;
#pragma unroll
            for (int i = 0; i < 4; i++) {
                Areg[i] = *(const float4*)(Ag + k0 + i * 4);
                Breg[i] = *(const float4*)(Wg + k0 + i * 4);
            }
        }

        const char* bb = smem + (c & 1) * TG_BUF;
#pragma unroll
        for (int ks = 0; ks < 32; ks += 16) {
            uint32_t aH[2][4], aL[2][4];
#pragma unroll
            for (int mi = 0; mi < 2; mi++) {
                const uint32_t row = (uint32_t)(wm * 32 + mi * 16 + r);
                const uint32_t o = row * RP + (uint32_t)(ks + 2 * q) * 2;
                aH[mi][0] = *(const uint32_t*)(bb + o);
                aH[mi][1] = *(const uint32_t*)(bb + o + 8 * RP);
                aH[mi][2] = *(const uint32_t*)(bb + o + 16);
                aH[mi][3] = *(const uint32_t*)(bb + o + 8 * RP + 16);
                aL[mi][0] = *(const uint32_t*)(bb + 10240 + o);
                aL[mi][1] = *(const uint32_t*)(bb + 10240 + o + 8 * RP);
                aL[mi][2] = *(const uint32_t*)(bb + 10240 + o + 16);
                aL[mi][3] = *(const uint32_t*)(bb + 10240 + o + 8 * RP + 16);
            }
            uint32_t bH[8][2], bL[8][2];
#pragma unroll
            for (int ni = 0; ni < 8; ni++) {
                const uint32_t n = (uint32_t)(wn * 64 + ni * 8 + r);
                const uint32_t o = n * RP + (uint32_t)(ks + 2 * q) * 2;
                bH[ni][0] = *(const uint32_t*)(bb + 20480 + o);
                bH[ni][1] = *(const uint32_t*)(bb + 20480 + o + 16);
                bL[ni][0] = *(const uint32_t*)(bb + 30720 + o);
                bL[ni][1] = *(const uint32_t*)(bb + 30720 + o + 16);
            }
#pragma unroll
            for (int mi = 0; mi < 2; mi++)
#pragma unroll
                for (int ni = 0; ni < 8; ni++) {
                    mma16816(acc[mi][ni], aH[mi], bH[ni]);
                    mma16816(acc[mi][ni], aH[mi], bL[ni]);
                    mma16816(acc[mi][ni], aL[mi], bH[ni]);
                }
        }

        if (c + 1 < nc) {
            char* wb = smem + ((c + 1) & 1) * TG_BUF;
            const uint32_t off0 = (uint32_t)srow * RP + (uint32_t)kb * 2;
#pragma unroll
            for (int i = 0; i < 4; i++) {
                uint32_t h01, h23, l01, l23;
                cvt_hilo4(Areg[i], h01, h23, l01, l23);
                const uint32_t o = off0 + i * 8;
                *(uint32_t*)(wb + o) = h01;
                *(uint32_t*)(wb + o + 4) = h23;
                *(uint32_t*)(wb + 10240 + o) = l01;
                *(uint32_t*)(wb + 10240 + o + 4) = l23;
                cvt_hilo4(Breg[i], h01, h23, l01, l23);
                *(uint32_t*)(wb + 20480 + o) = h01;
                *(uint32_t*)(wb + 20480 + o + 4) = h23;
                *(uint32_t*)(wb + 30720 + o) = l01;
                *(uint32_t*)(wb + 30720 + o + 4) = l23;
            }
            __syncthreads();
        }
    }

#pragma unroll
    for (int mi = 0; mi < 2; mi++) {
        const int rbase = row0 + wm * 32 + mi * 16 + r;
#pragma unroll
        for (int ni = 0; ni < 8; ni++) {
            const int col = col0 + wn * 64 + ni * 8 + 2 * q;
            float2 bv = *(const float2*)(bias + col);
            float o0 = acc[mi][ni][0] + bv.x;
            float o1 = acc[mi][ni][1] + bv.y;
            float o2 = acc[mi][ni][2] + bv.x;
            float o3 = acc[mi][ni][3] + bv.y;
            if (EPI == 1) {
                o0 = fmaxf(o0, 0.f); o1 = fmaxf(o1, 0.f);
                o2 = fmaxf(o2, 0.f); o3 = fmaxf(o3, 0.f);
            }
            if (EPI == 2) {
                float2 r0 = *(const float2*)(R + (size_t)rbase * ldr + col);
                float2 r1 = *(const float2*)(R + (size_t)(rbase + 8) * ldr + col);
                o0 += r0.x; o1 += r0.y; o2 += r1.x; o3 += r1.y;
            }
            if (EPI == 3) {
                uint32_t* Cp = (uint32_t*)C;
                *(uint2*)(Cp + (size_t)rbase * ldc + col) =
                    make_uint2(pack_hilo(o0), pack_hilo(o1));
                *(uint2*)(Cp + (size_t)(rbase + 8) * ldc + col) =
                    make_uint2(pack_hilo(o2), pack_hilo(o3));
            } else {
                *(float2*)(C + (size_t)rbase * ldc + col) = make_float2(o0, o1);
                *(float2*)(C + (size_t)(rbase + 8) * ldc + col) = make_float2(o2, o3);
            }
        }
    }
}

// ====================== fused flash attention (HMMA) ======================
// qkv arrives PACKED ((hi16<<16)|lo16 per element): unpack via __byte_perm,
// no cvt chains, half the global bytes. Q scale 1/8 applied post-MMA (exact).
// QH 0 / QL 20480 / KH 40960 / KL 61440 / VH 81920 / VL 102400 -> 122880 B.
#define FA_SMEM 122880

__global__ __launch_bounds__(256, 1) void flash_attn(
    const uint32_t* __restrict__ qkvp, float* __restrict__ ctx)
{
    extern __shared__ __align__(16) char smem[];
    const int tid = threadIdx.x;
    const int lane = tid & 31;
    const int w = tid >> 5;
    const int r = lane >> 2;
    const int q = lane & 3;
    const int bh = blockIdx.y;
    const int b = bh >> 4;
    const int h = bh & 15;
    const int qt = gridDim.x - 1 - blockIdx.x;  // long blocks first

    const uint32_t* Qg = qkvp + (size_t)b * SS * D3 + h * DH;
    const uint32_t* Kg = Qg + DD;
    const uint32_t* Vg = Qg + 2 * DD;

    // ---- load Q tile (packed -> hi/lo planes via byte_perm) ----
    {
        const int srow = tid >> 1;
        const int c = tid & 1;
        const uint32_t* src = Qg + (size_t)(qt * 128 + srow) * D3 + c * 32;
        char* dh = smem + c * 10240 + srow * RP;
        char* dl = smem + 20480 + c * 10240 + srow * RP;
#pragma unroll
        for (int i = 0; i < 8; i++) {
            uint4 v = *(const uint4*)(src + i * 4);
            uint32_t h01 = __byte_perm(v.x, v.y, 0x7632);
            uint32_t h23 = __byte_perm(v.z, v.w, 0x7632);
            uint32_t l01 = __byte_perm(v.x, v.y, 0x5410);
            uint32_t l23 = __byte_perm(v.z, v.w, 0x5410);
            *(uint2*)(dh + i * 8) = make_uint2(h01, h23);
            *(uint2*)(dl + i * 8) = make_uint2(l01, l23);
        }
    }
    __syncthreads();

    // ---- hoist Q fragments into registers ----
    uint32_t Qh[4][4], Ql[4][4];
#pragma unroll
    for (int kc = 0; kc < 4; kc++) {
        const int cc = kc >> 1;
        const int ks = (kc & 1) * 16;
        const char* Ah = smem + cc * 10240 + (w * 16 + r) * RP + (ks + 2 * q) * 2;
        const char* Al = Ah + 20480;
        Qh[kc][0] = *(const uint32_t*)(Ah);
        Qh[kc][1] = *(const uint32_t*)(Ah + 8 * RP);
        Qh[kc][2] = *(const uint32_t*)(Ah + 16);
        Qh[kc][3] = *(const uint32_t*)(Ah + 8 * RP + 16);
        Ql[kc][0] = *(const uint32_t*)(Al);
        Ql[kc][1] = *(const uint32_t*)(Al + 8 * RP);
        Ql[kc][2] = *(const uint32_t*)(Al + 16);
        Ql[kc][3] = *(const uint32_t*)(Al + 8 * RP + 16);
    }

    float Oacc[8][4];
#pragma unroll
    for (int ni = 0; ni < 8; ni++)
#pragma unroll
        for (int j = 0; j < 4; j++) Oacc[ni][j] = 0.f;
    float m0 = -1e30f, m1 = -1e30f, l0 = 0.f, l1 = 0.f;

    for (int kt = 0; kt <= qt; kt++) {
        __syncthreads();
        // ---- K tile (packed -> hi/lo planes) ----
        {
            const int srow = tid >> 1;
            const int c = tid & 1;
            const uint32_t* src = Kg + (size_t)(kt * 128 + srow) * D3 + c * 32;
            char* dh = smem + 40960 + c * 10240 + srow * RP;
            char* dl = smem + 61440 + c * 10240 + srow * RP;
#pragma unroll
            for (int i = 0; i < 8; i++) {
                uint4 v = *(const uint4*)(src + i * 4);
                uint32_t h01 = __byte_perm(v.x, v.y, 0x7632);
                uint32_t h23 = __byte_perm(v.z, v.w, 0x7632);
                uint32_t l01 = __byte_perm(v.x, v.y, 0x5410);
                uint32_t l23 = __byte_perm(v.z, v.w, 0x5410);
                *(uint2*)(dh + i * 8) = make_uint2(h01, h23);
                *(uint2*)(dl + i * 8) = make_uint2(l01, l23);
            }
        }
        // ---- V tile transposed (packed; lane-consecutive d, paired s) ----
        {
            const int d = tid & 63;
            const int sb = tid >> 6;
            const uint32_t* src = Vg + (size_t)(kt * 128 + sb * 32) * D3 + d;
            char* dh = smem + 81920 + sb * 5120 + d * RP;
            char* dl = smem + 102400 + sb * 5120 + d * RP;
#pragma unroll
            for (int j = 0; j < 32; j += 2) {
                uint32_t w0 = src[(size_t)j * D3];
                uint32_t w1 = src[(size_t)(j + 1) * D3];
                *(uint32_t*)(dh + j * 2) = __byte_perm(w0, w1, 0x7632);
                *(uint32_t*)(dl + j * 2) = __byte_perm(w0, w1, 0x5410);
            }
        }
        __syncthreads();

        // ---- S = Q K^T (3-pass hi/lo); skip fully-masked frags on diag ----
        float S[16][4];
#pragma unroll
        for (int ni = 0; ni < 16; ni++)
#pragma unroll
            for (int j = 0; j < 4; j++) S[ni][j] = 0.f;

        const bool diag = (kt == qt);
        const int rowmax = w * 16 + 15;

#pragma unroll
        for (int kc = 0; kc < 4; kc++) {
            const int cc = kc >> 1;
            const int ks = (kc & 1) * 16;
            const char* Bh = smem + 40960 + cc * 10240;
            const char* Bl = smem + 61440 + cc * 10240;
#pragma unroll
            for (int ni = 0; ni < 16; ni += 2) {
                if (diag && ni * 8 > rowmax) break;
                const uint32_t o0 = (uint32_t)(ni * 8 + r) * RP + (ks + 2 * q) * 2;
                const uint32_t o1 = (uint32_t)((ni + 1) * 8 + r) * RP + (ks + 2 * q) * 2;
                uint32_t bh0[2] = {*(const uint32_t*)(Bh + o0), *(const uint32_t*)(Bh + o0 + 16)};
                uint32_t bh1[2] = {*(const uint32_t*)(Bh + o1), *(const uint32_t*)(Bh + o1 + 16)};
                uint32_t bl0[2] = {*(const uint32_t*)(Bl + o0), *(const uint32_t*)(Bl + o0 + 16)};
                uint32_t bl1[2] = {*(const uint32_t*)(Bl + o1), *(const uint32_t*)(Bl + o1 + 16)};
                mma16816(S[ni], Qh[kc], bh0);     mma16816(S[ni + 1], Qh[kc], bh1);
                mma16816(S[ni], Qh[kc], bl0);     mma16816(S[ni + 1], Qh[kc], bl1);
                mma16816(S[ni], Ql[kc], bh0);     mma16816(S[ni + 1], Ql[kc], bh1);
            }
        }

        // ---- scale by 1/sqrt(dh)=0.125 (exact power of two) ----
#pragma unroll
        for (int ni = 0; ni < 16; ni++) {
            S[ni][0] *= 0.125f; S[ni][1] *= 0.125f;
            S[ni][2] *= 0.125f; S[ni][3] *= 0.125f;
        }

        // ---- causal mask on diagonal tile ----
        if (diag) {
            const int row0 = w * 16 + r;
#pragma unroll
            for (int ni = 0; ni < 16; ni++) {
                const int c0 = ni * 8 + 2 * q;
                if (c0 > row0)     S[ni][0] = -1e30f;
                if (c0 + 1 > row0) S[ni][1] = -1e30f;
                if (c0 > row0 + 8)     S[ni][2] = -1e30f;
                if (c0 + 1 > row0 + 8) S[ni][3] = -1e30f;
            }
        }

        // ---- online softmax ----
        float mx0 = -1e30f, mx1 = -1e30f;
#pragma unroll
        for (int ni = 0; ni < 16; ni++) {
            mx0 = fmaxf(mx0, fmaxf(S[ni][0], S[ni][1]));
            mx1 = fmaxf(mx1, fmaxf(S[ni][2], S[ni][3]));
        }
        mx0 = fmaxf(mx0, __shfl_xor_sync(0xffffffffu, mx0, 1));
        mx0 = fmaxf(mx0, __shfl_xor_sync(0xffffffffu, mx0, 2));
        mx1 = fmaxf(mx1, __shfl_xor_sync(0xffffffffu, mx1, 1));
        mx1 = fmaxf(mx1, __shfl_xor_sync(0xffffffffu, mx1, 2));
        const float mn0 = fmaxf(m0, mx0);
        const float mn1 = fmaxf(m1, mx1);
        const float a0 = __expf(m0 - mn0);
        const float a1 = __expf(m1 - mn1);
        m0 = mn0; m1 = mn1;
#pragma unroll
        for (int ni = 0; ni < 8; ni++) {
            Oacc[ni][0] *= a0; Oacc[ni][1] *= a0;
            Oacc[ni][2] *= a1; Oacc[ni][3] *= a1;
        }
        float s0 = 0.f, s1 = 0.f;
#pragma unroll
        for (int ni = 0; ni < 16; ni++) {
            S[ni][0] = __expf(S[ni][0] - m0);
            S[ni][1] = __expf(S[ni][1] - m0);
            S[ni][2] = __expf(S[ni][2] - m1);
            S[ni][3] = __expf(S[ni][3] - m1);
            s0 += S[ni][0] + S[ni][1];
            s1 += S[ni][2] + S[ni][3];
        }
        s0 += __shfl_xor_sync(0xffffffffu, s0, 1);
        s0 += __shfl_xor_sync(0xffffffffu, s0, 2);
        s1 += __shfl_xor_sync(0xffffffffu, s1, 1);
        s1 += __shfl_xor_sync(0xffffffffu, s1, 2);
        l0 = l0 * a0 + s0;
        l1 = l1 * a1 + s1;

        // ---- O += P @ V; on diag tile skip kc blocks where P == 0 ----
#pragma unroll
        for (int kc = 0; kc < 8; kc++) {
            if (diag && kc * 16 > rowmax) break;
            uint32_t aH[4], aL[4];
            aH[0] = packpair(S[2 * kc][0],     S[2 * kc][1],     aL[0]);
            aH[1] = packpair(S[2 * kc][2],     S[2 * kc][3],     aL[1]);
            aH[2] = packpair(S[2 * kc + 1][0], S[2 * kc + 1][1], aL[2]);
            aH[3] = packpair(S[2 * kc + 1][2], S[2 * kc + 1][3], aL[3]);
            const int cc = kc >> 1;
            const int ks = (kc & 1) * 16;
            const char* Bh = smem + 81920 + cc * 5120;
            const char* Bl = smem + 102400 + cc * 5120;
#pragma unroll
            for (int ni = 0; ni < 8; ni += 2) {
                const uint32_t o0 = (uint32_t)(ni * 8 + r) * RP + (ks + 2 * q) * 2;
                const uint32_t o1 = (uint32_t)((ni + 1) * 8 + r) * RP + (ks + 2 * q) * 2;
                uint32_t bh0[2] = {*(const uint32_t*)(Bh + o0), *(const uint32_t*)(Bh + o0 + 16)};
                uint32_t bh1[2] = {*(const uint32_t*)(Bh + o1), *(const uint32_t*)(Bh + o1 + 16)};
                uint32_t bl0[2] = {*(const uint32_t*)(Bl + o0), *(const uint32_t*)(Bl + o0 + 16)};
                uint32_t bl1[2] = {*(const uint32_t*)(Bl + o1), *(const uint32_t*)(Bl + o1 + 16)};
                mma16816(Oacc[ni], aH, bh0);     mma16816(Oacc[ni + 1], aH, bh1);
                mma16816(Oacc[ni], aH, bl0);     mma16816(Oacc[ni + 1], aH, bl1);
                mma16816(Oacc[ni], aL, bh0);     mma16816(Oacc[ni + 1], aL, bh1);
            }
        }
    }

    const float inv0 = 1.f / l0;
    const float inv1 = 1.f / l1;
    const int rowg = qt * 128 + w * 16 + r;
    float* O0 = ctx + ((size_t)b * SS + rowg) * DD + h * DH;
    float* O1 = O0 + (size_t)8 * DD;
#pragma unroll
    for (int ni = 0; ni < 8; ni++) {
        const int col = ni * 8 + 2 * q;
        *(float2*)(O0 + col) = make_float2(Oacc[ni][0] * inv0, Oacc[ni][1] * inv0);
        *(float2*)(O1 + col) = make_float2(Oacc[ni][2] * inv1, Oacc[ni][3] * inv1);
    }
}

// ---------------- LayerNorm over D=1024 -----------------------------------
__global__ __launch_bounds__(256) void layernorm_k(
    const float* __restrict__ x, const float* __restrict__ w,
    const float* __restrict__ b, float* __restrict__ out)
{
    const size_t row = blockIdx.x;
    const float* px = x + row * DD;
    float* po = out + row * DD;
    const int tid = threadIdx.x;

    float4 v = *(const float4*)(px + tid * 4);
    float s = v.x + v.y + v.z + v.w;
    float sq = v.x * v.x + v.y * v.y + v.z * v.z + v.w * v.w;

    __shared__ float rs[256];
    __shared__ float rq[256];
    rs[tid] = s;
    rq[tid] = sq;
    __syncthreads();
    for (int st = 128; st > 0; st >>= 1) {
        if (tid < st) { rs[tid] += rs[tid + st]; rq[tid] += rq[tid + st]; }
        __syncthreads();
    }
    const float mean = rs[0] * (1.f / DD);
    const float var = rq[0] * (1.f / DD) - mean * mean;
    const float rstd = rsqrtf(var + 1e-5f);

    float4 wv = *(const float4*)(w + tid * 4);
    float4 bv = *(const float4*)(b + tid * 4);
    float4 o;
    o.x = (v.x - mean) * rstd * wv.x + bv.x;
    o.y = (v.y - mean) * rstd * wv.y + bv.y;
    o.z = (v.z - mean) * rstd * wv.z + bv.z;
    o.w = (v.w - mean) * rstd * wv.w + bv.w;
    *(float4*)(po + tid * 4) = o;
}

// --------------------------------- driver ---------------------------------
extern "C" void kernel_launch(void* const* d_in, const int* in_sizes, int n_in,
                              void* d_out, int out_size)
{
    (void)in_sizes; (void)n_in; (void)out_size;
    const float* x     = (const float*)d_in[0];
    const float* qkv_w = (const float*)d_in[1];
    const float* qkv_b = (const float*)d_in[2];
    const float* out_w = (const float*)d_in[3];
    const float* out_b = (const float*)d_in[4];
    const float* w1    = (const float*)d_in[5];
    const float* b1    = (const float*)d_in[6];
    const float* w2    = (const float*)d_in[7];
    const float* b2    = (const float*)d_in[8];
    const float* ln1w  = (const float*)d_in[9];
    const float* ln1b  = (const float*)d_in[10];
    const float* ln2w  = (const float*)d_in[11];
    const float* ln2b  = (const float*)d_in[12];
    float* out = (float*)d_out;

    float *h, *qkv, *ctx, *tmp, *mlp;
    cudaGetSymbolAddress((void**)&h, g_h);
    cudaGetSymbolAddress((void**)&qkv, g_qkv);
    cudaGetSymbolAddress((void**)&ctx, g_ctx);
    cudaGetSymbolAddress((void**)&tmp, g_tmp);
    cudaGetSymbolAddress((void**)&mlp, g_mlp);

    cudaFuncSetAttribute(tgemm<1>, cudaFuncAttributeMaxDynamicSharedMemorySize, TG_SMEM);
    cudaFuncSetAttribute(tgemm<2>, cudaFuncAttributeMaxDynamicSharedMemorySize, TG_SMEM);
    cudaFuncSetAttribute(tgemm<3>, cudaFuncAttributeMaxDynamicSharedMemorySize, TG_SMEM);
    cudaFuncSetAttribute(flash_attn, cudaFuncAttributeMaxDynamicSharedMemorySize, FA_SMEM);

    const size_t act_bytes = (size_t)BB * SS * DD * sizeof(float);
    cudaMemcpyAsync(h, x, act_bytes, cudaMemcpyDeviceToDevice);

    const int M = BB * SS;

    for (int l = 0; l < NL; l++) {
        const float* lqw = qkv_w + (size_t)l * D3 * DD;
        const float* lqb = qkv_b + (size_t)l * D3;
        const float* low = out_w + (size_t)l * DD * DD;
        const float* lob = out_b + (size_t)l * DD;
        const float* lw1 = w1 + (size_t)l * DFF * DD;
        const float* lb1 = b1 + (size_t)l * DFF;
        const float* lw2 = w2 + (size_t)l * DD * DFF;
        const float* lb2 = b2 + (size_t)l * DD;

        // qkv (PACKED bf16 hi/lo) = h @ qkv_w^T + qkv_b
        tgemm<3><<<dim3(D3 / 128, M / 128), 256, TG_SMEM>>>(
            h, DD, lqw, DD, lqb, nullptr, 0, qkv, D3, DD);

        flash_attn<<<dim3(SS / 128, BB * NH), 256, FA_SMEM>>>((const uint32_t*)qkv, ctx);

        tgemm<2><<<dim3(DD / 128, M / 128), 256, TG_SMEM>>>(
            ctx, DD, low, DD, lob, h, DD, tmp, DD, DD);
        layernorm_k<<<M, 256>>>(tmp, ln1w + (size_t)l * DD, ln1b + (size_t)l * DD, h);

        tgemm<1><<<dim3(DFF / 128, M / 128), 256, TG_SMEM>>>(
            h, DD, lw1, DD, lb1, nullptr, 0, mlp, DFF, DD);

        tgemm<2><<<dim3(DD / 128, M / 128), 256, TG_SMEM>>>(
            mlp, DFF, lw2, DFF, lb2, h, DD, tmp, DD, DFF);
        layernorm_k<<<M, 256>>>(tmp, ln2w + (size_t)l * DD, ln2b + (size_t)l * DD, h);
    }

    cudaMemcpyAsync(out, h, act_bytes, cudaMemcpyDeviceToDevice);
}